// round 8
// baseline (speedup 1.0000x reference)
#include <cuda_runtime.h>
#include <math.h>
#include <stdint.h>

// Problem shape (fixed by the reference).
#define BB   2
#define HH   16
#define SS   2048
#define DD   64
#define TILE 64
#define NT   (SS / TILE)   // 32 tiles per sequence

#define PAD  68            // smem row stride (floats); 272B, 16B-aligned
#define PPAD 66            // PP row stride (ulls); 528B, 16B-aligned

typedef unsigned long long ull;

// Per-row softmax stats (written by kernel A, read by kernel B).
__device__ float g_m[BB * HH * SS];
__device__ float g_l[BB * HH * SS];
// Fallback scratch for raw scores if the harness output only holds `out`.
__device__ float g_scores[(size_t)BB * HH * SS * SS];

// ---- packed f32x2 helpers (sm_103a: PTX-only; ptxas never auto-fuses) ----
#define PACK2(dst, x, y) \
    asm("mov.b64 %0, {%1, %2};" : "=l"(dst) : "r"(__float_as_uint(x)), "r"(__float_as_uint(y)))
#define FMA2(acc, a, b) \
    asm("fma.rn.f32x2 %0, %1, %2, %3;" : "=l"(acc) : "l"(a), "l"(b), "l"(acc))
#define UNPK2(lo, hi, v) \
    asm("mov.b64 {%0, %1}, %2;" : "=r"(lo), "=r"(hi) : "l"(v))

// ---- cp.async helpers ----
__device__ __forceinline__ void cp16(uint32_t dst, const void* src) {
    asm volatile("cp.async.cg.shared.global [%0], [%1], 16;" :: "r"(dst), "l"(src));
}
__device__ __forceinline__ void cp_commit() { asm volatile("cp.async.commit_group;"); }
__device__ __forceinline__ void cp_wait1()  { asm volatile("cp.async.wait_group 1;"); }
__device__ __forceinline__ void cp_wait0()  { asm volatile("cp.async.wait_group 0;"); }

// ===========================================================================
// Kernel A: raw scores -> attn buffer + per-row (m,l) stats in registers.
// Packed-pair operands loaded directly as ulonglong2 (no MOV packing).
// ===========================================================================
__global__ void __launch_bounds__(256) attn_scores_kernel(
    const float* __restrict__ q,
    const float* __restrict__ k,
    float* __restrict__ attn)
{
    extern __shared__ float sm[];
    float* Qs  = sm;                  // [i][d], stride PAD
    float* Ks0 = sm + TILE * PAD;     // [j][d], stride PAD (double-buffered)
    float* Ks1 = Ks0 + TILE * PAD;

    const int bh = blockIdx.y;
    const int qt = (NT - 1) - blockIdx.x;   // heavy-first
    const int q0 = qt * TILE;
    const int tid = threadIdx.x;
    const int tx = tid & 15, ty = tid >> 4;

    const float* qb = q + ((size_t)bh * SS + q0) * DD;
    const float* kb = k + (size_t)bh * SS * DD;
    float* ab = attn + ((size_t)bh * SS + q0) * SS;

    uint32_t ks_u[2];
    ks_u[0] = (uint32_t)__cvta_generic_to_shared(Ks0);
    ks_u[1] = (uint32_t)__cvta_generic_to_shared(Ks1);

    // Load Q tile (row-major, padded)
    {
        const float4* src = (const float4*)qb;
        for (int c = tid; c < TILE * 16; c += 256) {
            int i = c >> 4, cc = c & 15;
            *(float4*)&Qs[i * PAD + cc * 4] = src[i * 16 + cc];
        }
    }
    // Prefetch K tile 0
    {
        const float4* src = (const float4*)kb;
        for (int c = tid; c < TILE * 16; c += 256) {
            int j = c >> 4, cc = c & 15;
            cp16(ks_u[0] + (uint32_t)(j * PAD + cc * 4) * 4u, src + (j * 16 + cc));
        }
        cp_commit();
    }

    float m_r[4] = {-INFINITY, -INFINITY, -INFINITY, -INFINITY};
    float l_r[4] = {0.f, 0.f, 0.f, 0.f};

    for (int kt = 0; kt <= qt; ++kt) {
        const int buf = kt & 1;
        if (kt < qt) {
            const float4* src = (const float4*)(kb + (size_t)(kt + 1) * TILE * DD);
            for (int c = tid; c < TILE * 16; c += 256) {
                int j = c >> 4, cc = c & 15;
                cp16(ks_u[buf ^ 1] + (uint32_t)(j * PAD + cc * 4) * 4u, src + (j * 16 + cc));
            }
            cp_commit();
            cp_wait1();
        } else {
            cp_wait0();
        }
        __syncthreads();

        const float* Kb = buf ? Ks1 : Ks0;

        // QK^T: operand pairs (d,d+1) read straight from smem as ulls.
        ull acc2[4][4];
        #pragma unroll
        for (int ii = 0; ii < 4; ++ii)
            #pragma unroll
            for (int jj = 0; jj < 4; ++jj) acc2[ii][jj] = 0ull;

        #pragma unroll 4
        for (int d = 0; d < DD; d += 4) {
            ulonglong2 qv[4], kv[4];
            #pragma unroll
            for (int ii = 0; ii < 4; ++ii)
                qv[ii] = *(const ulonglong2*)&Qs[(ty + 16 * ii) * PAD + d];
            #pragma unroll
            for (int jj = 0; jj < 4; ++jj)
                kv[jj] = *(const ulonglong2*)&Kb[(tx + 16 * jj) * PAD + d];
            #pragma unroll
            for (int ii = 0; ii < 4; ++ii)
                #pragma unroll
                for (int jj = 0; jj < 4; ++jj) {
                    FMA2(acc2[ii][jj], qv[ii].x, kv[jj].x);
                    FMA2(acc2[ii][jj], qv[ii].y, kv[jj].y);
                }
        }

        // Fold halves, scale, mask, store raw scores, update register (m,l).
        #pragma unroll
        for (int ii = 0; ii < 4; ++ii) {
            const int rloc = ty + 16 * ii;
            const int row  = q0 + rloc;
            float s[4];
            #pragma unroll
            for (int jj = 0; jj < 4; ++jj) {
                uint32_t lo, hi; UNPK2(lo, hi, acc2[ii][jj]);
                float val = (__uint_as_float(lo) + __uint_as_float(hi)) * 0.125f;
                int col = kt * TILE + tx + 16 * jj;
                if (col > row) val = -INFINITY;   // causal
                s[jj] = val;
                __stcs(&ab[(size_t)rloc * SS + col], val);
            }
            float mt = fmaxf(fmaxf(s[0], s[1]), fmaxf(s[2], s[3]));
            float mn = fmaxf(m_r[ii], mt);
            if (mn != -INFINITY) {
                l_r[ii] = l_r[ii] * __expf(m_r[ii] - mn)
                        + __expf(s[0] - mn) + __expf(s[1] - mn)
                        + __expf(s[2] - mn) + __expf(s[3] - mn);
                m_r[ii] = mn;
            }
        }
        __syncthreads();   // Kb reads done before next prefetch overwrites it
    }

    // Cross-lane reduce over the 16 tx lanes sharing each row.
    #pragma unroll
    for (int ii = 0; ii < 4; ++ii) {
        float m1 = m_r[ii], l1 = l_r[ii];
        #pragma unroll
        for (int off = 1; off < 16; off <<= 1) {
            float m2 = __shfl_xor_sync(0xffffffffu, m1, off);
            float l2 = __shfl_xor_sync(0xffffffffu, l1, off);
            float mn = fmaxf(m1, m2);
            float ln = (mn == -INFINITY) ? 0.f
                       : (l1 * __expf(m1 - mn) + l2 * __expf(m2 - mn));
            m1 = mn; l1 = ln;
        }
        if (tx == 0) {
            g_m[(size_t)bh * SS + q0 + ty + 16 * ii] = m1;
            g_l[(size_t)bh * SS + q0 + ty + 16 * ii] = l1;
        }
    }
}

// ===========================================================================
// Kernel B: normalize (raw s -> p) into a DUPLICATED-pair PP smem buffer +
// gmem attn; PV FMA reads pp via single LDS.64 broadcast (no packing MOVs),
// V as ulonglong2. Zero-fill above-diagonal tiles; write out.
// ===========================================================================
__global__ void __launch_bounds__(256) attn_pv_kernel(
    const float* __restrict__ v,
    float* __restrict__ attn,
    float* __restrict__ out)
{
    extern __shared__ float sm[];
    float* Ss0 = sm;                     // raw score tile [r][c], stride PAD
    float* Ss1 = Ss0 + TILE * PAD;
    float* Vs0 = Ss1 + TILE * PAD;       // V tile [k][d], stride PAD
    float* Vs1 = Vs0 + TILE * PAD;
    ull*   PP  = (ull*)(sm + 4 * TILE * PAD);       // [r][kk] dup pairs
    float* m_row  = sm + 4 * TILE * PAD + 2 * TILE * PPAD;  // PP = TILE*PPAD ulls
    float* il_row = m_row + TILE;

    const int bh = blockIdx.y;
    const int qt = (NT - 1) - blockIdx.x;   // heavy-first
    const int q0 = qt * TILE;
    const int tid = threadIdx.x;
    const int tx = tid & 15, ty = tid >> 4;

    float* ab = attn + ((size_t)bh * SS + q0) * SS;
    const float* vb = v + (size_t)bh * SS * DD;

    uint32_t ss_u[2], vs_u[2];
    ss_u[0] = (uint32_t)__cvta_generic_to_shared(Ss0);
    ss_u[1] = (uint32_t)__cvta_generic_to_shared(Ss1);
    vs_u[0] = (uint32_t)__cvta_generic_to_shared(Vs0);
    vs_u[1] = (uint32_t)__cvta_generic_to_shared(Vs1);

    if (tid < TILE) {
        size_t ridx = (size_t)bh * SS + q0 + tid;
        m_row[tid]  = g_m[ridx];
        il_row[tid] = 1.0f / g_l[ridx];
    }

    // Prefetch tile 0 (scores + V) as one group.
    {
        const float4* srcS = (const float4*)ab;
        const float4* srcV = (const float4*)vb;
        for (int c = tid; c < TILE * 16; c += 256) {
            int r = c >> 4, cc = c & 15;
            cp16(ss_u[0] + (uint32_t)(r * PAD + cc * 4) * 4u, srcS + ((size_t)r * (SS / 4) + cc));
            cp16(vs_u[0] + (uint32_t)(r * PAD + cc * 4) * 4u, srcV + (r * 16 + cc));
        }
        cp_commit();
    }

    ull acc2[4][2];
    #pragma unroll
    for (int ii = 0; ii < 4; ++ii) { acc2[ii][0] = 0ull; acc2[ii][1] = 0ull; }

    for (int kt = 0; kt <= qt; ++kt) {
        const int buf = kt & 1;
        if (kt < qt) {
            const float4* srcS = (const float4*)(ab + (size_t)(kt + 1) * TILE);
            const float4* srcV = (const float4*)(vb + (size_t)(kt + 1) * TILE * DD);
            for (int c = tid; c < TILE * 16; c += 256) {
                int r = c >> 4, cc = c & 15;
                cp16(ss_u[buf ^ 1] + (uint32_t)(r * PAD + cc * 4) * 4u, srcS + ((size_t)r * (SS / 4) + cc));
                cp16(vs_u[buf ^ 1] + (uint32_t)(r * PAD + cc * 4) * 4u, srcV + (r * 16 + cc));
            }
            cp_commit();
            cp_wait1();
        } else {
            cp_wait0();
        }
        __syncthreads();   // S/V[buf] ready; prior FMA (PP, V[buf^1]) finished

        const float* Sb = buf ? Ss1 : Ss0;
        const float* Vb = buf ? Vs1 : Vs0;

        // Normalize: raw s -> p; write dup-pairs to PP and final attn to gmem.
        for (int c = tid; c < TILE * 16; c += 256) {
            int r = c >> 4, cc = c & 15;
            float4 s4 = *(const float4*)&Sb[r * PAD + cc * 4];
            float m = m_row[r], il = il_row[r];
            float4 p;
            p.x = __expf(s4.x - m) * il;
            p.y = __expf(s4.y - m) * il;
            p.z = __expf(s4.z - m) * il;
            p.w = __expf(s4.w - m) * il;
            ull* pp = &PP[r * PPAD + cc * 4];
            PACK2(pp[0], p.x, p.x);
            PACK2(pp[1], p.y, p.y);
            PACK2(pp[2], p.z, p.z);
            PACK2(pp[3], p.w, p.w);
            __stcs((float4*)&ab[(size_t)r * SS + kt * TILE + cc * 4], p);
        }
        __syncthreads();   // PP ready

        // PV: acc[i][d-pair] += PP[i][kk] * V[kk][d-pair]
        #pragma unroll 8
        for (int kk = 0; kk < TILE; ++kk) {
            ulonglong2 vv = *(const ulonglong2*)&Vb[kk * PAD + tx * 4];
            #pragma unroll
            for (int ii = 0; ii < 4; ++ii) {
                ull pp = PP[(ty + 16 * ii) * PPAD + kk];   // LDS.64 broadcast
                FMA2(acc2[ii][0], pp, vv.x);
                FMA2(acc2[ii][1], pp, vv.y);
            }
        }
        __syncthreads();   // PP/V reads done before next iteration overwrites
    }

    // Zero-fill strictly-above-diagonal tiles (d_out poisoned 0xAA).
    const float4 z = make_float4(0.f, 0.f, 0.f, 0.f);
    for (int zt = qt + 1; zt < NT; ++zt) {
        for (int c = tid; c < TILE * 16; c += 256) {
            int r = c >> 4, cc = c & 15;
            __stcs((float4*)&ab[(size_t)r * SS + zt * TILE + cc * 4], z);
        }
    }

    // Write out tile.
    float* ob = out + ((size_t)bh * SS + q0) * DD;
    #pragma unroll
    for (int ii = 0; ii < 4; ++ii) {
        uint32_t lo, hi;
        float o0, o1, o2, o3;
        UNPK2(lo, hi, acc2[ii][0]); o0 = __uint_as_float(lo); o1 = __uint_as_float(hi);
        UNPK2(lo, hi, acc2[ii][1]); o2 = __uint_as_float(lo); o3 = __uint_as_float(hi);
        *(float4*)&ob[(size_t)(ty + 16 * ii) * DD + tx * 4] = make_float4(o0, o1, o2, o3);
    }
}

// ---------------------------------------------------------------------------
// Launch. Output layout [out | attn] (validated round 2); fallback kept.
// ---------------------------------------------------------------------------
extern "C" void kernel_launch(void* const* d_in, const int* in_sizes, int n_in,
                              void* d_out, int out_size)
{
    const float* q = (const float*)d_in[0];
    const float* k = (const float*)d_in[1];
    const float* v = (const float*)d_in[2];
    float* out = (float*)d_out;

    const size_t out_elems  = (size_t)BB * HH * SS * DD;
    const size_t attn_elems = (size_t)BB * HH * SS * SS;

    float* attn;
    if ((size_t)out_size >= out_elems + attn_elems) {
        attn = out + out_elems;
    } else {
        void* p = nullptr;
        cudaGetSymbolAddress(&p, g_scores);
        attn = (float*)p;
    }

    const int A_SMEM = 3 * TILE * PAD * 4;                                   // 52224 B
    const int B_SMEM = (4 * TILE * PAD + 2 * TILE * PPAD + 2 * TILE) * 4;    // 103936 B
    cudaFuncSetAttribute(attn_scores_kernel,
                         cudaFuncAttributeMaxDynamicSharedMemorySize, A_SMEM);
    cudaFuncSetAttribute(attn_pv_kernel,
                         cudaFuncAttributeMaxDynamicSharedMemorySize, B_SMEM);

    dim3 grid(NT, BB * HH);
    dim3 block(256);
    attn_scores_kernel<<<grid, block, A_SMEM>>>(q, k, attn);
    attn_pv_kernel<<<grid, block, B_SMEM>>>(v, attn, out);
}

// round 11
// speedup vs baseline: 1.0073x; 1.0073x over previous
#include <cuda_runtime.h>
#include <math.h>
#include <stdint.h>

// Problem shape (fixed by the reference).
#define BB   2
#define HH   16
#define SS   2048
#define DD   64
#define TILE 64
#define NT   (SS / TILE)   // 32 tiles per sequence

#define PAD  68            // smem row stride (floats); 272B, 16B-aligned

typedef unsigned long long ull;

// Per-row softmax stats (written by kernel A, read by kernel B).
__device__ float g_m[BB * HH * SS];
__device__ float g_l[BB * HH * SS];
// Fallback scratch for raw scores if the harness output only holds `out`.
__device__ float g_scores[(size_t)BB * HH * SS * SS];

// ---- packed f32x2 helpers (sm_103a: PTX-only; ptxas never auto-fuses) ----
#define PACK2(dst, x, y) \
    asm("mov.b64 %0, {%1, %2};" : "=l"(dst) : "r"(__float_as_uint(x)), "r"(__float_as_uint(y)))
#define FMA2(acc, a, b) \
    asm("fma.rn.f32x2 %0, %1, %2, %3;" : "=l"(acc) : "l"(a), "l"(b), "l"(acc))
#define UNPK2(lo, hi, v) \
    asm("mov.b64 {%0, %1}, %2;" : "=r"(lo), "=r"(hi) : "l"(v))

// ---- cp.async helpers ----
__device__ __forceinline__ void cp16(uint32_t dst, const void* src) {
    asm volatile("cp.async.cg.shared.global [%0], [%1], 16;" :: "r"(dst), "l"(src));
}
__device__ __forceinline__ void cp_commit() { asm volatile("cp.async.commit_group;"); }
__device__ __forceinline__ void cp_wait1()  { asm volatile("cp.async.wait_group 1;"); }
__device__ __forceinline__ void cp_wait0()  { asm volatile("cp.async.wait_group 0;"); }

// ===========================================================================
// Kernel A: raw scores -> attn buffer + per-row (m,l) stats in registers.
// 128 threads. Thread (tx,ty) owns rows {ty+16*ii, ii<4}, cols {tx+8*jj, jj<8}.
// Per warp: Q loads broadcast over 8 tx lanes; K loads conflict-free
// (bank = 4*tx + d with PAD=68). 5.3 MAC/smem-byte (was 1.78).
// ===========================================================================
__global__ void __launch_bounds__(128) attn_scores_kernel(
    const float* __restrict__ q,
    const float* __restrict__ k,
    float* __restrict__ attn)
{
    extern __shared__ float sm[];
    float* Qs  = sm;                  // [i][d], stride PAD
    float* Ks0 = sm + TILE * PAD;     // [j][d], stride PAD (double-buffered)
    float* Ks1 = Ks0 + TILE * PAD;

    const int bh = blockIdx.y;
    const int qt = (NT - 1) - blockIdx.x;   // heavy-first
    const int q0 = qt * TILE;
    const int tid = threadIdx.x;
    const int tx = tid & 7;        // col group (8)
    const int ty = tid >> 3;       // row group (16)

    const float* qb = q + ((size_t)bh * SS + q0) * DD;
    const float* kb = k + (size_t)bh * SS * DD;
    float* ab = attn + ((size_t)bh * SS + q0) * SS;

    uint32_t ks_u[2];
    ks_u[0] = (uint32_t)__cvta_generic_to_shared(Ks0);
    ks_u[1] = (uint32_t)__cvta_generic_to_shared(Ks1);

    // Load Q tile (row-major, padded)
    {
        const float4* src = (const float4*)qb;
        for (int c = tid; c < TILE * 16; c += 128) {
            int i = c >> 4, cc = c & 15;
            *(float4*)&Qs[i * PAD + cc * 4] = src[i * 16 + cc];
        }
    }
    // Prefetch K tile 0
    {
        const float4* src = (const float4*)kb;
        for (int c = tid; c < TILE * 16; c += 128) {
            int j = c >> 4, cc = c & 15;
            cp16(ks_u[0] + (uint32_t)(j * PAD + cc * 4) * 4u, src + (j * 16 + cc));
        }
        cp_commit();
    }

    float m_r[4] = {-INFINITY, -INFINITY, -INFINITY, -INFINITY};
    float l_r[4] = {0.f, 0.f, 0.f, 0.f};

    for (int kt = 0; kt <= qt; ++kt) {
        const int buf = kt & 1;
        if (kt < qt) {
            const float4* src = (const float4*)(kb + (size_t)(kt + 1) * TILE * DD);
            for (int c = tid; c < TILE * 16; c += 128) {
                int j = c >> 4, cc = c & 15;
                cp16(ks_u[buf ^ 1] + (uint32_t)(j * PAD + cc * 4) * 4u, src + (j * 16 + cc));
            }
            cp_commit();
            cp_wait1();
        } else {
            cp_wait0();
        }
        __syncthreads();

        const float* Kb = buf ? Ks1 : Ks0;

        // QK^T: 32 outputs/thread, packed over (d, d+1) reduction pairs.
        ull acc2[4][8];
        #pragma unroll
        for (int ii = 0; ii < 4; ++ii)
            #pragma unroll
            for (int jj = 0; jj < 8; ++jj) acc2[ii][jj] = 0ull;

        #pragma unroll 2
        for (int d = 0; d < DD; d += 4) {
            ulonglong2 qv[4];
            #pragma unroll
            for (int ii = 0; ii < 4; ++ii)
                qv[ii] = *(const ulonglong2*)&Qs[(ty + 16 * ii) * PAD + d];
            ulonglong2 kv[8];
            #pragma unroll
            for (int jj = 0; jj < 8; ++jj)
                kv[jj] = *(const ulonglong2*)&Kb[(tx + 8 * jj) * PAD + d];
            #pragma unroll
            for (int ii = 0; ii < 4; ++ii)
                #pragma unroll
                for (int jj = 0; jj < 8; ++jj) {
                    FMA2(acc2[ii][jj], qv[ii].x, kv[jj].x);
                    FMA2(acc2[ii][jj], qv[ii].y, kv[jj].y);
                }
        }

        // Fold halves, scale, mask, store raw scores, update register (m,l).
        #pragma unroll
        for (int ii = 0; ii < 4; ++ii) {
            const int rloc = ty + 16 * ii;
            const int row  = q0 + rloc;
            float s[8];
            #pragma unroll
            for (int jj = 0; jj < 8; ++jj) {
                uint32_t lo, hi; UNPK2(lo, hi, acc2[ii][jj]);
                float val = (__uint_as_float(lo) + __uint_as_float(hi)) * 0.125f;
                int col = kt * TILE + tx + 8 * jj;
                if (col > row) val = -INFINITY;   // causal
                s[jj] = val;
                __stcs(&ab[(size_t)rloc * SS + col], val);
            }
            float mt = s[0];
            #pragma unroll
            for (int jj = 1; jj < 8; ++jj) mt = fmaxf(mt, s[jj]);
            float mn = fmaxf(m_r[ii], mt);
            if (mn != -INFINITY) {
                float lsum = 0.f;
                #pragma unroll
                for (int jj = 0; jj < 8; ++jj) lsum += __expf(s[jj] - mn);
                l_r[ii] = l_r[ii] * __expf(m_r[ii] - mn) + lsum;
                m_r[ii] = mn;
            }
        }
        __syncthreads();   // Kb reads done before next prefetch overwrites it
    }

    // Cross-lane reduce over the 8 tx lanes sharing each row.
    #pragma unroll
    for (int ii = 0; ii < 4; ++ii) {
        float m1 = m_r[ii], l1 = l_r[ii];
        #pragma unroll
        for (int off = 1; off < 8; off <<= 1) {
            float m2 = __shfl_xor_sync(0xffffffffu, m1, off);
            float l2 = __shfl_xor_sync(0xffffffffu, l1, off);
            float mn = fmaxf(m1, m2);
            float ln = (mn == -INFINITY) ? 0.f
                       : (l1 * __expf(m1 - mn) + l2 * __expf(m2 - mn));
            m1 = mn; l1 = ln;
        }
        if (tx == 0) {
            g_m[(size_t)bh * SS + q0 + ty + 16 * ii] = m1;
            g_l[(size_t)bh * SS + q0 + ty + 16 * ii] = l1;
        }
    }
}

// ===========================================================================
// Kernel B: normalize in place (raw s -> p in smem + gmem attn), then
// out = P @ V. 128 threads; thread owns rows {ty+16*ii} x d-cols tx*8..+7.
// Per kk: 2 LDS.128 (V) + 4 broadcast LDS.32 (P) feed 16 FFMA2.
// ===========================================================================
__global__ void __launch_bounds__(128) attn_pv_kernel(
    const float* __restrict__ v,
    float* __restrict__ attn,
    float* __restrict__ out)
{
    extern __shared__ float sm[];
    float* Ss0 = sm;                     // score/P tile [r][c], stride PAD
    float* Ss1 = Ss0 + TILE * PAD;
    float* Vs0 = Ss1 + TILE * PAD;       // V tile [k][d], stride PAD
    float* Vs1 = Vs0 + TILE * PAD;
    float* m_row  = Vs1 + TILE * PAD;    // 64
    float* il_row = m_row + TILE;        // 64

    const int bh = blockIdx.y;
    const int qt = (NT - 1) - blockIdx.x;   // heavy-first
    const int q0 = qt * TILE;
    const int tid = threadIdx.x;
    const int tx = tid & 7;        // d group (8 cols each)
    const int ty = tid >> 3;       // row group (16)

    float* ab = attn + ((size_t)bh * SS + q0) * SS;
    const float* vb = v + (size_t)bh * SS * DD;

    uint32_t ss_u[2], vs_u[2];
    ss_u[0] = (uint32_t)__cvta_generic_to_shared(Ss0);
    ss_u[1] = (uint32_t)__cvta_generic_to_shared(Ss1);
    vs_u[0] = (uint32_t)__cvta_generic_to_shared(Vs0);
    vs_u[1] = (uint32_t)__cvta_generic_to_shared(Vs1);

    if (tid < TILE) {
        size_t ridx = (size_t)bh * SS + q0 + tid;
        m_row[tid]  = g_m[ridx];
        il_row[tid] = 1.0f / g_l[ridx];
    }

    // Prefetch tile 0 (scores + V) as one group.
    {
        const float4* srcS = (const float4*)ab;
        const float4* srcV = (const float4*)vb;
        for (int c = tid; c < TILE * 16; c += 128) {
            int r = c >> 4, cc = c & 15;
            cp16(ss_u[0] + (uint32_t)(r * PAD + cc * 4) * 4u, srcS + ((size_t)r * (SS / 4) + cc));
            cp16(vs_u[0] + (uint32_t)(r * PAD + cc * 4) * 4u, srcV + (r * 16 + cc));
        }
        cp_commit();
    }

    ull acc2[4][4];
    #pragma unroll
    for (int ii = 0; ii < 4; ++ii)
        #pragma unroll
        for (int p2 = 0; p2 < 4; ++p2) acc2[ii][p2] = 0ull;

    for (int kt = 0; kt <= qt; ++kt) {
        const int buf = kt & 1;
        if (kt < qt) {
            const float4* srcS = (const float4*)(ab + (size_t)(kt + 1) * TILE);
            const float4* srcV = (const float4*)(vb + (size_t)(kt + 1) * TILE * DD);
            for (int c = tid; c < TILE * 16; c += 128) {
                int r = c >> 4, cc = c & 15;
                cp16(ss_u[buf ^ 1] + (uint32_t)(r * PAD + cc * 4) * 4u, srcS + ((size_t)r * (SS / 4) + cc));
                cp16(vs_u[buf ^ 1] + (uint32_t)(r * PAD + cc * 4) * 4u, srcV + (r * 16 + cc));
            }
            cp_commit();
            cp_wait1();
        } else {
            cp_wait0();
        }
        __syncthreads();

        float* Sb = buf ? Ss1 : Ss0;
        const float* Vb = buf ? Vs1 : Vs0;

        // Normalize in place: raw s -> p; also write final attn to gmem.
        for (int c = tid; c < TILE * 16; c += 128) {
            int r = c >> 4, cc = c & 15;
            float4 s4 = *(const float4*)&Sb[r * PAD + cc * 4];
            float m = m_row[r], il = il_row[r];
            float4 p;
            p.x = __expf(s4.x - m) * il;
            p.y = __expf(s4.y - m) * il;
            p.z = __expf(s4.z - m) * il;
            p.w = __expf(s4.w - m) * il;
            *(float4*)&Sb[r * PAD + cc * 4] = p;
            __stcs((float4*)&ab[(size_t)r * SS + kt * TILE + cc * 4], p);
        }
        __syncthreads();

        // PV: acc[i][pair] += P[i][kk] * V[kk][pair]
        #pragma unroll 4
        for (int kk = 0; kk < TILE; ++kk) {
            ulonglong2 v0 = *(const ulonglong2*)&Vb[kk * PAD + tx * 8];
            ulonglong2 v1 = *(const ulonglong2*)&Vb[kk * PAD + tx * 8 + 4];
            #pragma unroll
            for (int ii = 0; ii < 4; ++ii) {
                float p = Sb[(ty + 16 * ii) * PAD + kk];   // broadcast over tx
                ull pp; PACK2(pp, p, p);
                FMA2(acc2[ii][0], pp, v0.x);
                FMA2(acc2[ii][1], pp, v0.y);
                FMA2(acc2[ii][2], pp, v1.x);
                FMA2(acc2[ii][3], pp, v1.y);
            }
        }
        __syncthreads();   // Sb/Vb reads done before next iteration overwrites
    }

    // Zero-fill strictly-above-diagonal tiles (d_out poisoned 0xAA).
    const float4 z = make_float4(0.f, 0.f, 0.f, 0.f);
    for (int zt = qt + 1; zt < NT; ++zt) {
        for (int c = tid; c < TILE * 16; c += 128) {
            int r = c >> 4, cc = c & 15;
            __stcs((float4*)&ab[(size_t)r * SS + zt * TILE + cc * 4], z);
        }
    }

    // Write out tile: rows ty+16ii, cols tx*8..tx*8+7.
    float* ob = out + ((size_t)bh * SS + q0) * DD;
    #pragma unroll
    for (int ii = 0; ii < 4; ++ii) {
        uint32_t lo, hi;
        float o[8];
        UNPK2(lo, hi, acc2[ii][0]); o[0] = __uint_as_float(lo); o[1] = __uint_as_float(hi);
        UNPK2(lo, hi, acc2[ii][1]); o[2] = __uint_as_float(lo); o[3] = __uint_as_float(hi);
        UNPK2(lo, hi, acc2[ii][2]); o[4] = __uint_as_float(lo); o[5] = __uint_as_float(hi);
        UNPK2(lo, hi, acc2[ii][3]); o[6] = __uint_as_float(lo); o[7] = __uint_as_float(hi);
        float* op = &ob[(size_t)(ty + 16 * ii) * DD + tx * 8];
        *(float4*)op       = make_float4(o[0], o[1], o[2], o[3]);
        *(float4*)(op + 4) = make_float4(o[4], o[5], o[6], o[7]);
    }
}

// ---------------------------------------------------------------------------
// Launch. Output layout [out | attn] (validated round 2); fallback kept.
// ---------------------------------------------------------------------------
extern "C" void kernel_launch(void* const* d_in, const int* in_sizes, int n_in,
                              void* d_out, int out_size)
{
    const float* q = (const float*)d_in[0];
    const float* k = (const float*)d_in[1];
    const float* v = (const float*)d_in[2];
    float* out = (float*)d_out;

    const size_t out_elems  = (size_t)BB * HH * SS * DD;
    const size_t attn_elems = (size_t)BB * HH * SS * SS;

    float* attn;
    if ((size_t)out_size >= out_elems + attn_elems) {
        attn = out + out_elems;
    } else {
        void* p = nullptr;
        cudaGetSymbolAddress(&p, g_scores);
        attn = (float*)p;
    }

    const int A_SMEM = 3 * TILE * PAD * 4;                 // 52224 B -> up to 4 CTAs/SM
    const int B_SMEM = (4 * TILE * PAD + 2 * TILE) * 4;    // 70144 B -> 3 CTAs/SM
    cudaFuncSetAttribute(attn_scores_kernel,
                         cudaFuncAttributeMaxDynamicSharedMemorySize, A_SMEM);
    cudaFuncSetAttribute(attn_pv_kernel,
                         cudaFuncAttributeMaxDynamicSharedMemorySize, B_SMEM);

    dim3 grid(NT, BB * HH);
    dim3 block(128);
    attn_scores_kernel<<<grid, block, A_SMEM>>>(q, k, attn);
    attn_pv_kernel<<<grid, block, B_SMEM>>>(v, attn, out);
}

// round 14
// speedup vs baseline: 1.1117x; 1.1037x over previous
#include <cuda_runtime.h>
#include <math.h>
#include <stdint.h>

// Problem shape (fixed by the reference).
#define BB   2
#define HH   16
#define SS   2048
#define DD   64
#define TILE 64
#define NT   (SS / TILE)   // 32 tiles per sequence

#define PAD  68            // smem row stride (floats); 272B, 16B-aligned

typedef unsigned long long ull;

// Per-row softmax stats (written by kernel A, read by kernel B).
__device__ float g_m[BB * HH * SS];
__device__ float g_l[BB * HH * SS];
// Fallback scratch for raw scores if the harness output only holds `out`.
__device__ float g_scores[(size_t)BB * HH * SS * SS];

// ---- packed f32x2 helpers (sm_103a: PTX-only; ptxas never auto-fuses) ----
#define PACK2(dst, x, y) \
    asm("mov.b64 %0, {%1, %2};" : "=l"(dst) : "r"(__float_as_uint(x)), "r"(__float_as_uint(y)))
#define FMA2(acc, a, b) \
    asm("fma.rn.f32x2 %0, %1, %2, %3;" : "=l"(acc) : "l"(a), "l"(b), "l"(acc))
#define UNPK2(lo, hi, v) \
    asm("mov.b64 {%0, %1}, %2;" : "=r"(lo), "=r"(hi) : "l"(v))

// ---- cp.async helpers ----
__device__ __forceinline__ void cp16(uint32_t dst, const void* src) {
    asm volatile("cp.async.cg.shared.global [%0], [%1], 16;" :: "r"(dst), "l"(src));
}
__device__ __forceinline__ void cp_commit() { asm volatile("cp.async.commit_group;"); }
__device__ __forceinline__ void cp_wait1()  { asm volatile("cp.async.wait_group 1;"); }
__device__ __forceinline__ void cp_wait0()  { asm volatile("cp.async.wait_group 0;"); }

// ===========================================================================
// Kernel A (identical to the measured-best R5 version, 328us):
// raw scores -> attn buffer + per-row (m,l) stats in registers.
// 256 threads; thread (tx,ty) owns rows {ty+16ii} x cols {tx+16jj}, 4x4.
// ===========================================================================
__global__ void __launch_bounds__(256) attn_scores_kernel(
    const float* __restrict__ q,
    const float* __restrict__ k,
    float* __restrict__ attn)
{
    extern __shared__ float sm[];
    float* Qs  = sm;                  // [i][d], stride PAD
    float* Ks0 = sm + TILE * PAD;     // [j][d], stride PAD (double-buffered)
    float* Ks1 = Ks0 + TILE * PAD;

    const int bh = blockIdx.y;
    const int qt = (NT - 1) - blockIdx.x;   // heavy-first
    const int q0 = qt * TILE;
    const int tid = threadIdx.x;
    const int tx = tid & 15, ty = tid >> 4;

    const float* qb = q + ((size_t)bh * SS + q0) * DD;
    const float* kb = k + (size_t)bh * SS * DD;
    float* ab = attn + ((size_t)bh * SS + q0) * SS;

    uint32_t ks_u[2];
    ks_u[0] = (uint32_t)__cvta_generic_to_shared(Ks0);
    ks_u[1] = (uint32_t)__cvta_generic_to_shared(Ks1);

    // Load Q tile (row-major, padded)
    {
        const float4* src = (const float4*)qb;
        for (int c = tid; c < TILE * 16; c += 256) {
            int i = c >> 4, cc = c & 15;
            *(float4*)&Qs[i * PAD + cc * 4] = src[i * 16 + cc];
        }
    }
    // Prefetch K tile 0
    {
        const float4* src = (const float4*)kb;
        for (int c = tid; c < TILE * 16; c += 256) {
            int j = c >> 4, cc = c & 15;
            cp16(ks_u[0] + (uint32_t)(j * PAD + cc * 4) * 4u, src + (j * 16 + cc));
        }
        cp_commit();
    }

    float m_r[4] = {-INFINITY, -INFINITY, -INFINITY, -INFINITY};
    float l_r[4] = {0.f, 0.f, 0.f, 0.f};

    for (int kt = 0; kt <= qt; ++kt) {
        const int buf = kt & 1;
        if (kt < qt) {
            const float4* src = (const float4*)(kb + (size_t)(kt + 1) * TILE * DD);
            for (int c = tid; c < TILE * 16; c += 256) {
                int j = c >> 4, cc = c & 15;
                cp16(ks_u[buf ^ 1] + (uint32_t)(j * PAD + cc * 4) * 4u, src + (j * 16 + cc));
            }
            cp_commit();
            cp_wait1();
        } else {
            cp_wait0();
        }
        __syncthreads();

        const float* Kb = buf ? Ks1 : Ks0;

        // QK^T: operand pairs (d,d+1) read straight from smem as ulls.
        ull acc2[4][4];
        #pragma unroll
        for (int ii = 0; ii < 4; ++ii)
            #pragma unroll
            for (int jj = 0; jj < 4; ++jj) acc2[ii][jj] = 0ull;

        #pragma unroll 4
        for (int d = 0; d < DD; d += 4) {
            ulonglong2 qv[4], kv[4];
            #pragma unroll
            for (int ii = 0; ii < 4; ++ii)
                qv[ii] = *(const ulonglong2*)&Qs[(ty + 16 * ii) * PAD + d];
            #pragma unroll
            for (int jj = 0; jj < 4; ++jj)
                kv[jj] = *(const ulonglong2*)&Kb[(tx + 16 * jj) * PAD + d];
            #pragma unroll
            for (int ii = 0; ii < 4; ++ii)
                #pragma unroll
                for (int jj = 0; jj < 4; ++jj) {
                    FMA2(acc2[ii][jj], qv[ii].x, kv[jj].x);
                    FMA2(acc2[ii][jj], qv[ii].y, kv[jj].y);
                }
        }

        // Fold halves, scale, mask, store raw scores, update register (m,l).
        #pragma unroll
        for (int ii = 0; ii < 4; ++ii) {
            const int rloc = ty + 16 * ii;
            const int row  = q0 + rloc;
            float s[4];
            #pragma unroll
            for (int jj = 0; jj < 4; ++jj) {
                uint32_t lo, hi; UNPK2(lo, hi, acc2[ii][jj]);
                float val = (__uint_as_float(lo) + __uint_as_float(hi)) * 0.125f;
                int col = kt * TILE + tx + 16 * jj;
                if (col > row) val = -INFINITY;   // causal
                s[jj] = val;
                __stcs(&ab[(size_t)rloc * SS + col], val);
            }
            float mt = fmaxf(fmaxf(s[0], s[1]), fmaxf(s[2], s[3]));
            float mn = fmaxf(m_r[ii], mt);
            if (mn != -INFINITY) {
                l_r[ii] = l_r[ii] * __expf(m_r[ii] - mn)
                        + __expf(s[0] - mn) + __expf(s[1] - mn)
                        + __expf(s[2] - mn) + __expf(s[3] - mn);
                m_r[ii] = mn;
            }
        }
        __syncthreads();   // Kb reads done before next prefetch overwrites it
    }

    // Cross-lane reduce over the 16 tx lanes sharing each row.
    #pragma unroll
    for (int ii = 0; ii < 4; ++ii) {
        float m1 = m_r[ii], l1 = l_r[ii];
        #pragma unroll
        for (int off = 1; off < 16; off <<= 1) {
            float m2 = __shfl_xor_sync(0xffffffffu, m1, off);
            float l2 = __shfl_xor_sync(0xffffffffu, l1, off);
            float mn = fmaxf(m1, m2);
            float ln = (mn == -INFINITY) ? 0.f
                       : (l1 * __expf(m1 - mn) + l2 * __expf(m2 - mn));
            m1 = mn; l1 = ln;
        }
        if (tx == 0) {
            g_m[(size_t)bh * SS + q0 + ty + 16 * ii] = m1;
            g_l[(size_t)bh * SS + q0 + ty + 16 * ii] = l1;
        }
    }
}

// ===========================================================================
// Kernel B (restructured for occupancy): raw S is read DIRECTLY from gmem
// into registers (no smem staging), normalized, written back (STG) and
// stored once into a single P smem buffer for the PV GEMM. Only V is
// cp.async double-buffered. smem 52.7KB -> 4 CTAs/SM (forced), 32 warps.
// ===========================================================================
__global__ void __launch_bounds__(256, 4) attn_pv_kernel(
    const float* __restrict__ v,
    float* __restrict__ attn,
    float* __restrict__ out)
{
    extern __shared__ float sm[];
    float* Vs0 = sm;                     // V tile [k][d], stride PAD (dbl-buf)
    float* Vs1 = Vs0 + TILE * PAD;
    float* Ps  = Vs1 + TILE * PAD;       // P tile [r][c], stride PAD (single)
    float* m_row  = Ps + TILE * PAD;     // 64
    float* il_row = m_row + TILE;        // 64

    const int bh = blockIdx.y;
    const int qt = (NT - 1) - blockIdx.x;   // heavy-first
    const int q0 = qt * TILE;
    const int tid = threadIdx.x;
    const int tx = tid & 15, ty = tid >> 4;

    float* ab = attn + ((size_t)bh * SS + q0) * SS;
    const float* vb = v + (size_t)bh * SS * DD;

    uint32_t vs_u[2];
    vs_u[0] = (uint32_t)__cvta_generic_to_shared(Vs0);
    vs_u[1] = (uint32_t)__cvta_generic_to_shared(Vs1);

    if (tid < TILE) {
        size_t ridx = (size_t)bh * SS + q0 + tid;
        m_row[tid]  = g_m[ridx];
        il_row[tid] = 1.0f / g_l[ridx];
    }

    // Prefetch V tile 0.
    {
        const float4* srcV = (const float4*)vb;
        for (int c = tid; c < TILE * 16; c += 256) {
            int r = c >> 4, cc = c & 15;
            cp16(vs_u[0] + (uint32_t)(r * PAD + cc * 4) * 4u, srcV + (r * 16 + cc));
        }
        cp_commit();
    }
    __syncthreads();   // m_row/il_row visible to all

    ull acc2[4][2];
    #pragma unroll
    for (int ii = 0; ii < 4; ++ii) { acc2[ii][0] = 0ull; acc2[ii][1] = 0ull; }

    for (int kt = 0; kt <= qt; ++kt) {
        const int buf = kt & 1;
        if (kt < qt) {
            const float4* srcV = (const float4*)(vb + (size_t)(kt + 1) * TILE * DD);
            for (int c = tid; c < TILE * 16; c += 256) {
                int r = c >> 4, cc = c & 15;
                cp16(vs_u[buf ^ 1] + (uint32_t)(r * PAD + cc * 4) * 4u, srcV + (r * 16 + cc));
            }
            cp_commit();
            cp_wait1();
        } else {
            cp_wait0();
        }
        __syncthreads();   // V[buf] ready; prior PV reads of Ps/V[buf^1] done

        const float* Vb = buf ? Vs1 : Vs0;

        // Normalize straight from gmem: LDG raw s -> p; STG final attn; STS P.
        #pragma unroll 4
        for (int c = tid; c < TILE * 16; c += 256) {
            int r = c >> 4, cc = c & 15;
            float* gp = &ab[(size_t)r * SS + kt * TILE + cc * 4];
            float4 s4 = __ldcs((const float4*)gp);
            float m = m_row[r], il = il_row[r];
            float4 p;
            p.x = __expf(s4.x - m) * il;
            p.y = __expf(s4.y - m) * il;
            p.z = __expf(s4.z - m) * il;
            p.w = __expf(s4.w - m) * il;
            __stcs((float4*)gp, p);
            *(float4*)&Ps[r * PAD + cc * 4] = p;
        }
        __syncthreads();   // Ps ready

        // PV: acc[i][d-pair] += P[i][kk] * V[kk][d-pair]
        #pragma unroll 8
        for (int kk = 0; kk < TILE; ++kk) {
            ulonglong2 vv = *(const ulonglong2*)&Vb[kk * PAD + tx * 4];
            #pragma unroll
            for (int ii = 0; ii < 4; ++ii) {
                float p = Ps[(ty + 16 * ii) * PAD + kk];   // 16-lane broadcast
                ull pp; PACK2(pp, p, p);
                FMA2(acc2[ii][0], pp, vv.x);
                FMA2(acc2[ii][1], pp, vv.y);
            }
        }
        __syncthreads();   // Ps/Vb reads done before next iteration overwrites
    }

    // Zero-fill strictly-above-diagonal tiles (d_out poisoned 0xAA).
    const float4 z = make_float4(0.f, 0.f, 0.f, 0.f);
    for (int zt = qt + 1; zt < NT; ++zt) {
        for (int c = tid; c < TILE * 16; c += 256) {
            int r = c >> 4, cc = c & 15;
            __stcs((float4*)&ab[(size_t)r * SS + zt * TILE + cc * 4], z);
        }
    }

    // Write out tile.
    float* ob = out + ((size_t)bh * SS + q0) * DD;
    #pragma unroll
    for (int ii = 0; ii < 4; ++ii) {
        uint32_t lo, hi;
        float o0, o1, o2, o3;
        UNPK2(lo, hi, acc2[ii][0]); o0 = __uint_as_float(lo); o1 = __uint_as_float(hi);
        UNPK2(lo, hi, acc2[ii][1]); o2 = __uint_as_float(lo); o3 = __uint_as_float(hi);
        *(float4*)&ob[(size_t)(ty + 16 * ii) * DD + tx * 4] = make_float4(o0, o1, o2, o3);
    }
}

// ---------------------------------------------------------------------------
// Launch. Output layout [out | attn] (validated round 2); fallback kept.
// ---------------------------------------------------------------------------
extern "C" void kernel_launch(void* const* d_in, const int* in_sizes, int n_in,
                              void* d_out, int out_size)
{
    const float* q = (const float*)d_in[0];
    const float* k = (const float*)d_in[1];
    const float* v = (const float*)d_in[2];
    float* out = (float*)d_out;

    const size_t out_elems  = (size_t)BB * HH * SS * DD;
    const size_t attn_elems = (size_t)BB * HH * SS * SS;

    float* attn;
    if ((size_t)out_size >= out_elems + attn_elems) {
        attn = out + out_elems;
    } else {
        void* p = nullptr;
        cudaGetSymbolAddress(&p, g_scores);
        attn = (float*)p;
    }

    const int A_SMEM = 3 * TILE * PAD * 4;                 // 52224 B
    const int B_SMEM = (3 * TILE * PAD + 2 * TILE) * 4;    // 52736 B -> 4 CTAs/SM
    cudaFuncSetAttribute(attn_scores_kernel,
                         cudaFuncAttributeMaxDynamicSharedMemorySize, A_SMEM);
    cudaFuncSetAttribute(attn_pv_kernel,
                         cudaFuncAttributeMaxDynamicSharedMemorySize, B_SMEM);

    dim3 grid(NT, BB * HH);
    dim3 block(256);
    attn_scores_kernel<<<grid, block, A_SMEM>>>(q, k, attn);
    attn_pv_kernel<<<grid, block, B_SMEM>>>(v, attn, out);
}

// round 15
// speedup vs baseline: 1.2097x; 1.0882x over previous
#include <cuda_runtime.h>
#include <math.h>
#include <stdint.h>

// Problem shape (fixed by the reference).
#define BB   2
#define HH   16
#define SS   2048
#define DD   64
#define TILE 64
#define NT   (SS / TILE)   // 32 tiles per sequence

#define PAD  68            // smem row stride (floats); 272B, 16B-aligned

typedef unsigned long long ull;

// Fallback scratch for raw scores if the harness output only holds `out`.
__device__ float g_scores[(size_t)BB * HH * SS * SS];

// ---- packed f32x2 helpers (sm_103a: PTX-only; ptxas never auto-fuses) ----
#define PACK2(dst, x, y) \
    asm("mov.b64 %0, {%1, %2};" : "=l"(dst) : "r"(__float_as_uint(x)), "r"(__float_as_uint(y)))
#define FMA2(acc, a, b) \
    asm("fma.rn.f32x2 %0, %1, %2, %3;" : "=l"(acc) : "l"(a), "l"(b), "l"(acc))
#define UNPK2(lo, hi, v) \
    asm("mov.b64 {%0, %1}, %2;" : "=r"(lo), "=r"(hi) : "l"(v))

// ---- cp.async helpers ----
__device__ __forceinline__ void cp16(uint32_t dst, const void* src) {
    asm volatile("cp.async.cg.shared.global [%0], [%1], 16;" :: "r"(dst), "l"(src));
}
__device__ __forceinline__ void cp_commit() { asm volatile("cp.async.commit_group;"); }
__device__ __forceinline__ void cp_wait1()  { asm volatile("cp.async.wait_group 1;"); }
__device__ __forceinline__ void cp_wait0()  { asm volatile("cp.async.wait_group 0;"); }

// ===========================================================================
// Fused kernel: one block handles one (bh, q-tile).
//  Pass 1 (== measured-best R5 kernel A): QK^T tiles -> raw scores to gmem
//          (PLAIN stores, so the lines stay L2-resident) + register (m,l).
//  Pass 2 (== measured-best R5 kernel B): cp.async-staged raw scores (now
//          L2-hot: this block just wrote them) + V; normalize in place,
//          write final attn (__stcs), accumulate out = P @ V.
// smem regions are reused across passes (sequential, sync-separated).
// ===========================================================================
__global__ void __launch_bounds__(256, 3) attn_fused_kernel(
    const float* __restrict__ q,
    const float* __restrict__ k,
    const float* __restrict__ v,
    float* __restrict__ attn,
    float* __restrict__ out)
{
    extern __shared__ float sm[];
    // Pass-1 view:
    float* Qs  = sm;                     // [i][d], stride PAD
    float* Ks0 = sm + TILE * PAD;
    float* Ks1 = sm + 2 * TILE * PAD;
    // Pass-2 view (aliases pass-1 regions; used strictly after sync):
    float* Ss0 = sm;
    float* Ss1 = sm + TILE * PAD;
    float* Vs0 = sm + 2 * TILE * PAD;
    float* Vs1 = sm + 3 * TILE * PAD;    // pass-2 only
    float* m_row  = sm + 4 * TILE * PAD; // 64 (outside pass-1 regions)
    float* il_row = m_row + TILE;        // 64

    const int bh = blockIdx.y;
    const int qt = (NT - 1) - blockIdx.x;   // heavy-first
    const int q0 = qt * TILE;
    const int tid = threadIdx.x;
    const int tx = tid & 15, ty = tid >> 4;

    const float* qb = q + ((size_t)bh * SS + q0) * DD;
    const float* kb = k + (size_t)bh * SS * DD;
    const float* vb = v + (size_t)bh * SS * DD;
    float* ab = attn + ((size_t)bh * SS + q0) * SS;

    uint32_t b0 = (uint32_t)__cvta_generic_to_shared(sm);
    const uint32_t R = (uint32_t)(TILE * PAD) * 4u;   // region stride in bytes

    // ---------------- Pass 1: scores + (m,l) ----------------
    {
        const float4* src = (const float4*)qb;
        for (int c = tid; c < TILE * 16; c += 256) {
            int i = c >> 4, cc = c & 15;
            *(float4*)&Qs[i * PAD + cc * 4] = src[i * 16 + cc];
        }
    }
    {
        const float4* src = (const float4*)kb;
        for (int c = tid; c < TILE * 16; c += 256) {
            int j = c >> 4, cc = c & 15;
            cp16(b0 + R + (uint32_t)(j * PAD + cc * 4) * 4u, src + (j * 16 + cc));
        }
        cp_commit();
    }

    float m_r[4] = {-INFINITY, -INFINITY, -INFINITY, -INFINITY};
    float l_r[4] = {0.f, 0.f, 0.f, 0.f};

    for (int kt = 0; kt <= qt; ++kt) {
        const int buf = kt & 1;
        if (kt < qt) {
            const float4* src = (const float4*)(kb + (size_t)(kt + 1) * TILE * DD);
            uint32_t dst = b0 + (buf ? R : 2u * R);   // other K buffer
            for (int c = tid; c < TILE * 16; c += 256) {
                int j = c >> 4, cc = c & 15;
                cp16(dst + (uint32_t)(j * PAD + cc * 4) * 4u, src + (j * 16 + cc));
            }
            cp_commit();
            cp_wait1();
        } else {
            cp_wait0();
        }
        __syncthreads();

        const float* Kb = buf ? Ks1 : Ks0;

        ull acc2[4][4];
        #pragma unroll
        for (int ii = 0; ii < 4; ++ii)
            #pragma unroll
            for (int jj = 0; jj < 4; ++jj) acc2[ii][jj] = 0ull;

        #pragma unroll 4
        for (int d = 0; d < DD; d += 4) {
            ulonglong2 qv[4], kv[4];
            #pragma unroll
            for (int ii = 0; ii < 4; ++ii)
                qv[ii] = *(const ulonglong2*)&Qs[(ty + 16 * ii) * PAD + d];
            #pragma unroll
            for (int jj = 0; jj < 4; ++jj)
                kv[jj] = *(const ulonglong2*)&Kb[(tx + 16 * jj) * PAD + d];
            #pragma unroll
            for (int ii = 0; ii < 4; ++ii)
                #pragma unroll
                for (int jj = 0; jj < 4; ++jj) {
                    FMA2(acc2[ii][jj], qv[ii].x, kv[jj].x);
                    FMA2(acc2[ii][jj], qv[ii].y, kv[jj].y);
                }
        }

        #pragma unroll
        for (int ii = 0; ii < 4; ++ii) {
            const int rloc = ty + 16 * ii;
            const int row  = q0 + rloc;
            float s[4];
            #pragma unroll
            for (int jj = 0; jj < 4; ++jj) {
                uint32_t lo, hi; UNPK2(lo, hi, acc2[ii][jj]);
                float val = (__uint_as_float(lo) + __uint_as_float(hi)) * 0.125f;
                int col = kt * TILE + tx + 16 * jj;
                if (col > row) val = -INFINITY;   // causal
                s[jj] = val;
                // PLAIN store: keep the line L2-resident for pass 2.
                ab[(size_t)rloc * SS + col] = val;
            }
            float mt = fmaxf(fmaxf(s[0], s[1]), fmaxf(s[2], s[3]));
            float mn = fmaxf(m_r[ii], mt);
            if (mn != -INFINITY) {
                l_r[ii] = l_r[ii] * __expf(m_r[ii] - mn)
                        + __expf(s[0] - mn) + __expf(s[1] - mn)
                        + __expf(s[2] - mn) + __expf(s[3] - mn);
                m_r[ii] = mn;
            }
        }
        __syncthreads();   // Kb consumed before next prefetch overwrites it
    }

    // (m,l) reduce over the 16 tx lanes sharing each row -> smem.
    #pragma unroll
    for (int ii = 0; ii < 4; ++ii) {
        float m1 = m_r[ii], l1 = l_r[ii];
        #pragma unroll
        for (int off = 1; off < 16; off <<= 1) {
            float m2 = __shfl_xor_sync(0xffffffffu, m1, off);
            float l2 = __shfl_xor_sync(0xffffffffu, l1, off);
            float mn = fmaxf(m1, m2);
            float ln = (mn == -INFINITY) ? 0.f
                       : (l1 * __expf(m1 - mn) + l2 * __expf(m2 - mn));
            m1 = mn; l1 = ln;
        }
        if (tx == 0) {
            m_row[ty + 16 * ii]  = m1;
            il_row[ty + 16 * ii] = 1.0f / l1;
        }
    }
    // Raw-score STGs + m/il smem writes visible block-wide after this.
    __syncthreads();

    // ---------------- Pass 2: normalize + PV ----------------
    {
        const float4* srcS = (const float4*)ab;
        const float4* srcV = (const float4*)vb;
        for (int c = tid; c < TILE * 16; c += 256) {
            int r = c >> 4, cc = c & 15;
            cp16(b0 +          (uint32_t)(r * PAD + cc * 4) * 4u, srcS + ((size_t)r * (SS / 4) + cc));
            cp16(b0 + 2u * R + (uint32_t)(r * PAD + cc * 4) * 4u, srcV + (r * 16 + cc));
        }
        cp_commit();
    }

    ull acc2[4][2];
    #pragma unroll
    for (int ii = 0; ii < 4; ++ii) { acc2[ii][0] = 0ull; acc2[ii][1] = 0ull; }

    for (int kt = 0; kt <= qt; ++kt) {
        const int buf = kt & 1;
        if (kt < qt) {
            const float4* srcS = (const float4*)(ab + (size_t)(kt + 1) * TILE);
            const float4* srcV = (const float4*)(vb + (size_t)(kt + 1) * TILE * DD);
            uint32_t dstS = b0 + (buf ? 0u : R);        // other S buffer
            uint32_t dstV = b0 + (buf ? 2u * R : 3u * R); // other V buffer
            for (int c = tid; c < TILE * 16; c += 256) {
                int r = c >> 4, cc = c & 15;
                cp16(dstS + (uint32_t)(r * PAD + cc * 4) * 4u, srcS + ((size_t)r * (SS / 4) + cc));
                cp16(dstV + (uint32_t)(r * PAD + cc * 4) * 4u, srcV + (r * 16 + cc));
            }
            cp_commit();
            cp_wait1();
        } else {
            cp_wait0();
        }
        __syncthreads();   // S/V[buf] ready; prior PV reads of old buffers done

        float* Sb = buf ? Ss1 : Ss0;
        const float* Vb = buf ? Vs1 : Vs0;

        // Normalize in place: raw s -> p; write final attn (stream, no reuse).
        for (int c = tid; c < TILE * 16; c += 256) {
            int r = c >> 4, cc = c & 15;
            float4 s4 = *(const float4*)&Sb[r * PAD + cc * 4];
            float m = m_row[r], il = il_row[r];
            float4 p;
            p.x = __expf(s4.x - m) * il;
            p.y = __expf(s4.y - m) * il;
            p.z = __expf(s4.z - m) * il;
            p.w = __expf(s4.w - m) * il;
            *(float4*)&Sb[r * PAD + cc * 4] = p;
            __stcs((float4*)&ab[(size_t)r * SS + kt * TILE + cc * 4], p);
        }
        __syncthreads();   // Ps ready

        #pragma unroll 8
        for (int kk = 0; kk < TILE; ++kk) {
            ulonglong2 vv = *(const ulonglong2*)&Vb[kk * PAD + tx * 4];
            #pragma unroll
            for (int ii = 0; ii < 4; ++ii) {
                float p = Sb[(ty + 16 * ii) * PAD + kk];   // 16-lane broadcast
                ull pp; PACK2(pp, p, p);
                FMA2(acc2[ii][0], pp, vv.x);
                FMA2(acc2[ii][1], pp, vv.y);
            }
        }
        __syncthreads();   // Sb/Vb reads done before next iteration overwrites
    }

    // Zero-fill strictly-above-diagonal tiles (d_out poisoned 0xAA).
    const float4 z = make_float4(0.f, 0.f, 0.f, 0.f);
    for (int zt = qt + 1; zt < NT; ++zt) {
        for (int c = tid; c < TILE * 16; c += 256) {
            int r = c >> 4, cc = c & 15;
            __stcs((float4*)&ab[(size_t)r * SS + zt * TILE + cc * 4], z);
        }
    }

    // Write out tile.
    float* ob = out + ((size_t)bh * SS + q0) * DD;
    #pragma unroll
    for (int ii = 0; ii < 4; ++ii) {
        uint32_t lo, hi;
        float o0, o1, o2, o3;
        UNPK2(lo, hi, acc2[ii][0]); o0 = __uint_as_float(lo); o1 = __uint_as_float(hi);
        UNPK2(lo, hi, acc2[ii][1]); o2 = __uint_as_float(lo); o3 = __uint_as_float(hi);
        *(float4*)&ob[(size_t)(ty + 16 * ii) * DD + tx * 4] = make_float4(o0, o1, o2, o3);
    }
}

// ---------------------------------------------------------------------------
// Launch. Output layout [out | attn] (validated round 2); fallback kept.
// ---------------------------------------------------------------------------
extern "C" void kernel_launch(void* const* d_in, const int* in_sizes, int n_in,
                              void* d_out, int out_size)
{
    const float* q = (const float*)d_in[0];
    const float* k = (const float*)d_in[1];
    const float* v = (const float*)d_in[2];
    float* out = (float*)d_out;

    const size_t out_elems  = (size_t)BB * HH * SS * DD;
    const size_t attn_elems = (size_t)BB * HH * SS * SS;

    float* attn;
    if ((size_t)out_size >= out_elems + attn_elems) {
        attn = out + out_elems;
    } else {
        void* p = nullptr;
        cudaGetSymbolAddress(&p, g_scores);
        attn = (float*)p;
    }

    const int SMEM = (4 * TILE * PAD + 2 * TILE) * 4;   // 70144 B -> 3 CTAs/SM
    cudaFuncSetAttribute(attn_fused_kernel,
                         cudaFuncAttributeMaxDynamicSharedMemorySize, SMEM);

    dim3 grid(NT, BB * HH);
    dim3 block(256);
    attn_fused_kernel<<<grid, block, SMEM>>>(q, k, v, attn, out);
}